// round 2
// baseline (speedup 1.0000x reference)
#include <cuda_runtime.h>
#include <math.h>

// Problem constants
#define B_  32
#define N_  512
#define H_  1024
#define E_  2048
#define S_  128
#define R_  (B_ * N_)          // 16384 rows
#define UVW (2 * E_ + S_)      // 4224
#define MAXSEQ 512

// ---------------- scratch (device globals; no allocations allowed) ----------
__device__ float g_xn[R_ * H_];          // layernorm output
__device__ float g_uv[R_ * UVW];         // silu(xn @ uv_w + uv_b); u|v|base slices
__device__ float g_q[R_ * S_];
__device__ float g_k[R_ * S_];
__device__ float g_ker[B_ * N_ * N_];    // relu^2 kernel matrix
__device__ float g_attn[R_ * E_];        // u * (kernel @ v)
__device__ float g_sin[N_ * 64];
__device__ float g_cos[N_ * 64];

// ---------------- sin/cos table (replicates reference fp32 arithmetic) ------
__global__ void sincos_kernel() {
    int i = blockIdx.x * 256 + threadIdx.x;   // < 512*64
    if (i >= N_ * 64) return;
    int d = i & 63;
    int pos = i >> 6;
    // correctly-rounded fp32 of 10000^(d/64)  (matches libm powf constant fold)
    float invf = (float)pow(10000.0, (double)d * (1.0 / 64.0));
    float arg = (float)pos * invf;            // exact fp32, same bits as reference
    g_sin[i] = (float)sin((double)arg);
    g_cos[i] = (float)cos((double)arg);
}

// ---------------- LayerNorm --------------------------------------------------
__global__ __launch_bounds__(256) void ln_kernel(
    const float* __restrict__ x, const float* __restrict__ ln_g,
    const float* __restrict__ ln_b)
{
    int row = blockIdx.x;
    const float4* xr = (const float4*)(x + (size_t)row * H_);
    float4 v = xr[threadIdx.x];
    float s = v.x + v.y + v.z + v.w;
    float sq = v.x * v.x + v.y * v.y + v.z * v.z + v.w * v.w;
    #pragma unroll
    for (int o = 16; o; o >>= 1) {
        s  += __shfl_down_sync(0xffffffffu, s, o);
        sq += __shfl_down_sync(0xffffffffu, sq, o);
    }
    __shared__ float ss[8], ssq[8];
    int wrp = threadIdx.x >> 5, l = threadIdx.x & 31;
    if (l == 0) { ss[wrp] = s; ssq[wrp] = sq; }
    __syncthreads();
    if (wrp == 0) {
        s  = (l < 8) ? ss[l] : 0.f;
        sq = (l < 8) ? ssq[l] : 0.f;
        #pragma unroll
        for (int o = 4; o; o >>= 1) {
            s  += __shfl_down_sync(0xffu, s, o);
            sq += __shfl_down_sync(0xffu, sq, o);
        }
        if (l == 0) { ss[0] = s; ssq[0] = sq; }
    }
    __syncthreads();
    float mu = ss[0] * (1.f / H_);
    float var = ssq[0] * (1.f / H_) - mu * mu;
    float rs = rsqrtf(var + 1e-5f);
    float4 g = ((const float4*)ln_g)[threadIdx.x];
    float4 bb = ((const float4*)ln_b)[threadIdx.x];
    float4 o;
    o.x = (v.x - mu) * rs * g.x + bb.x;
    o.y = (v.y - mu) * rs * g.y + bb.y;
    o.z = (v.z - mu) * rs * g.z + bb.z;
    o.w = (v.w - mu) * rs * g.w + bb.w;
    ((float4*)(g_xn + (size_t)row * H_))[threadIdx.x] = o;
}

// ---------------- 128x128 SGEMM core (256 threads, 8x8 microtile) -----------
// A: [M,K] row-major, caller pre-offsets to tile row.
// BT=false: B is [K,N] row-major, caller pre-offsets to tile col.
// BT=true : B is [N,K] row-major (NT gemm), caller pre-offsets to tile row.
template <bool BT>
__device__ __forceinline__ void gemm_tile(
    const float* __restrict__ A, int lda,
    const float* __restrict__ B, int ldb,
    int K, float acc[8][8])
{
    __shared__ float As[16][128];
    __shared__ float Bs[16][128];
    const int tid = threadIdx.x;
    const int tx = tid & 15, ty = tid >> 4;
    const int ar = tid >> 2;            // 0..63
    const int ac = (tid & 3) << 2;      // 0,4,8,12
    const int br = tid >> 5;            // 0..7
    const int bc = (tid & 31) << 2;     // 0..124

    for (int k0 = 0; k0 < K; k0 += 16) {
        float4 a0 = *(const float4*)(A + (size_t)ar * lda + k0 + ac);
        float4 a1 = *(const float4*)(A + (size_t)(ar + 64) * lda + k0 + ac);
        float4 b0, b1;
        if (BT) {
            b0 = *(const float4*)(B + (size_t)ar * ldb + k0 + ac);
            b1 = *(const float4*)(B + (size_t)(ar + 64) * ldb + k0 + ac);
        } else {
            b0 = *(const float4*)(B + (size_t)(k0 + br) * ldb + bc);
            b1 = *(const float4*)(B + (size_t)(k0 + br + 8) * ldb + bc);
        }
        __syncthreads();
        As[ac + 0][ar] = a0.x; As[ac + 1][ar] = a0.y;
        As[ac + 2][ar] = a0.z; As[ac + 3][ar] = a0.w;
        As[ac + 0][ar + 64] = a1.x; As[ac + 1][ar + 64] = a1.y;
        As[ac + 2][ar + 64] = a1.z; As[ac + 3][ar + 64] = a1.w;
        if (BT) {
            Bs[ac + 0][ar] = b0.x; Bs[ac + 1][ar] = b0.y;
            Bs[ac + 2][ar] = b0.z; Bs[ac + 3][ar] = b0.w;
            Bs[ac + 0][ar + 64] = b1.x; Bs[ac + 1][ar + 64] = b1.y;
            Bs[ac + 2][ar + 64] = b1.z; Bs[ac + 3][ar + 64] = b1.w;
        } else {
            *(float4*)&Bs[br][bc] = b0;
            *(float4*)&Bs[br + 8][bc] = b1;
        }
        __syncthreads();
        #pragma unroll
        for (int kk = 0; kk < 16; ++kk) {
            float4 aa0 = *(const float4*)&As[kk][ty * 8];
            float4 aa1 = *(const float4*)&As[kk][ty * 8 + 4];
            float4 bb0 = *(const float4*)&Bs[kk][tx * 8];
            float4 bb1 = *(const float4*)&Bs[kk][tx * 8 + 4];
            float a[8] = {aa0.x, aa0.y, aa0.z, aa0.w, aa1.x, aa1.y, aa1.z, aa1.w};
            float b[8] = {bb0.x, bb0.y, bb0.z, bb0.w, bb1.x, bb1.y, bb1.z, bb1.w};
            #pragma unroll
            for (int i = 0; i < 8; ++i)
                #pragma unroll
                for (int j = 0; j < 8; ++j)
                    acc[i][j] += a[i] * b[j];
        }
    }
}

// ---------------- GEMM 1: uv = silu(xn @ uv_w + uv_b) -----------------------
__global__ __launch_bounds__(256) void gemm_uv(
    const float* __restrict__ uv_w, const float* __restrict__ uv_b)
{
    const float* A = g_xn + (size_t)blockIdx.y * 128 * H_;
    const float* B = uv_w + (size_t)blockIdx.x * 128;
    float acc[8][8] = {};
    gemm_tile<false>(A, H_, B, UVW, H_, acc);
    const int tx = threadIdx.x & 15, ty = threadIdx.x >> 4;
    int row0 = blockIdx.y * 128 + ty * 8;
    int col0 = blockIdx.x * 128 + tx * 8;
    #pragma unroll
    for (int i = 0; i < 8; ++i) {
        #pragma unroll
        for (int j = 0; j < 8; ++j) {
            float v = acc[i][j] + uv_b[col0 + j];
            v = v / (1.f + expf(-v));          // silu
            g_uv[(size_t)(row0 + i) * UVW + col0 + j] = v;
        }
    }
}

// ---------------- RoPE on base -> q, k ---------------------------------------
__global__ __launch_bounds__(128) void rope_kernel(
    const float* __restrict__ gamma, const float* __restrict__ beta)
{
    int row = blockIdx.x;
    int t = threadIdx.x;   // 0..127
    __shared__ float pq[128], pk[128];
    float base = g_uv[(size_t)row * UVW + 2 * E_ + t];
    pq[t] = base * gamma[t]        + beta[t];
    pk[t] = base * gamma[128 + t]  + beta[128 + t];
    __syncthreads();
    int pos = row & (N_ - 1);
    if (t < 64) {
        float s = g_sin[pos * 64 + t], c = g_cos[pos * 64 + t];
        float x1 = pq[t], x2 = pq[t + 64];
        g_q[(size_t)row * S_ + t]      = x1 * c - x2 * s;
        g_q[(size_t)row * S_ + t + 64] = x2 * c + x1 * s;
    } else {
        int d = t - 64;
        float s = g_sin[pos * 64 + d], c = g_cos[pos * 64 + d];
        float x1 = pk[d], x2 = pk[d + 64];
        g_k[(size_t)row * S_ + d]      = x1 * c - x2 * s;
        g_k[(size_t)row * S_ + d + 64] = x2 * c + x1 * s;
    }
}

// ---------------- GEMM 2: scores = relu(q@k^T/512 + bias + mask)^2 ----------
__global__ __launch_bounds__(256) void gemm_scores(
    const float* __restrict__ w, const float* __restrict__ mask)
{
    int z = blockIdx.z;
    const float* A = g_q + (size_t)z * N_ * S_ + (size_t)blockIdx.y * 128 * S_;
    const float* B = g_k + (size_t)z * N_ * S_ + (size_t)blockIdx.x * 128 * S_;
    float acc[8][8] = {};
    gemm_tile<true>(A, S_, B, S_, S_, acc);
    const int tx = threadIdx.x & 15, ty = threadIdx.x >> 4;
    int n0 = blockIdx.y * 128 + ty * 8;
    int m0 = blockIdx.x * 128 + tx * 8;
    #pragma unroll
    for (int i = 0; i < 8; ++i) {
        int n = n0 + i;
        #pragma unroll
        for (int j = 0; j < 8; ++j) {
            int m = m0 + j;
            float sc = acc[i][j] * (1.f / MAXSEQ)
                     + w[m - n + (MAXSEQ - 1)]
                     + (1.f - mask[z * N_ + m]) * (-1e12f);
            sc = fmaxf(sc, 0.f);
            g_ker[(size_t)z * N_ * N_ + (size_t)n * N_ + m] = sc * sc;
        }
    }
}

// ---------------- GEMM 3: attn = u * (kernel @ v) ----------------------------
__global__ __launch_bounds__(256) void gemm_attn()
{
    int z = blockIdx.z;
    const float* A = g_ker + (size_t)z * N_ * N_ + (size_t)blockIdx.y * 128 * N_;
    const float* B = g_uv + (size_t)(z * N_) * UVW + E_ + (size_t)blockIdx.x * 128;
    float acc[8][8] = {};
    gemm_tile<false>(A, N_, B, UVW, N_, acc);
    const int tx = threadIdx.x & 15, ty = threadIdx.x >> 4;
    int n0 = blockIdx.y * 128 + ty * 8;
    int c0 = blockIdx.x * 128 + tx * 8;
    #pragma unroll
    for (int i = 0; i < 8; ++i) {
        int rg = z * N_ + n0 + i;
        #pragma unroll
        for (int j = 0; j < 8; ++j) {
            int c = c0 + j;
            float u = g_uv[(size_t)rg * UVW + c];
            g_attn[(size_t)rg * E_ + c] = acc[i][j] * u;
        }
    }
}

// ---------------- GEMM 4: out = attn @ o_w + o_b + x -------------------------
__global__ __launch_bounds__(256) void gemm_out(
    const float* __restrict__ o_w, const float* __restrict__ o_b,
    const float* __restrict__ x, float* __restrict__ out)
{
    const float* A = g_attn + (size_t)blockIdx.y * 128 * E_;
    const float* B = o_w + (size_t)blockIdx.x * 128;
    float acc[8][8] = {};
    gemm_tile<false>(A, E_, B, H_, E_, acc);
    const int tx = threadIdx.x & 15, ty = threadIdx.x >> 4;
    int row0 = blockIdx.y * 128 + ty * 8;
    int col0 = blockIdx.x * 128 + tx * 8;
    #pragma unroll
    for (int i = 0; i < 8; ++i) {
        int r = row0 + i;
        #pragma unroll
        for (int j = 0; j < 8; ++j) {
            int c = col0 + j;
            out[(size_t)r * H_ + c] = acc[i][j] + o_b[c] + x[(size_t)r * H_ + c];
        }
    }
}

// ---------------- launch -----------------------------------------------------
extern "C" void kernel_launch(void* const* d_in, const int* in_sizes, int n_in,
                              void* d_out, int out_size)
{
    const float* x     = (const float*)d_in[0];
    const float* mask  = (const float*)d_in[1];
    const float* gamma = (const float*)d_in[2];
    const float* beta  = (const float*)d_in[3];
    const float* w     = (const float*)d_in[4];
    // d_in[5] = a_p, d_in[6] = b_p : unused by reference
    const float* uv_w  = (const float*)d_in[7];
    const float* uv_b  = (const float*)d_in[8];
    const float* o_w   = (const float*)d_in[9];
    const float* o_b   = (const float*)d_in[10];
    const float* ln_g  = (const float*)d_in[11];
    const float* ln_b  = (const float*)d_in[12];
    float* out = (float*)d_out;

    sincos_kernel<<<128, 256>>>();
    ln_kernel<<<R_, 256>>>(x, ln_g, ln_b);
    gemm_uv<<<dim3(UVW / 128, R_ / 128), 256>>>(uv_w, uv_b);
    rope_kernel<<<R_, 128>>>(gamma, beta);
    gemm_scores<<<dim3(N_ / 128, N_ / 128, B_), 256>>>(w, mask);
    gemm_attn<<<dim3(E_ / 128, N_ / 128, B_), 256>>>();
    gemm_out<<<dim3(H_ / 128, R_ / 128), 256>>>(o_w, o_b, x, out);
}

// round 4
// speedup vs baseline: 2.0865x; 2.0865x over previous
#include <cuda_runtime.h>
#include <cuda_bf16.h>
#include <cstdint>
#include <math.h>

// Problem constants
#define B_  32
#define N_  512
#define H_  1024
#define E_  2048
#define S_  128
#define R_  (B_ * N_)          // 16384 rows
#define UVW (2 * E_ + S_)      // 4224
#define MAXSEQ 512

// ---------------- scratch (device globals; no allocations allowed) ----------
__device__ float g_xn[R_ * H_];
__device__ float g_uv[R_ * UVW];
__device__ float g_q[R_ * S_];
__device__ float g_k[R_ * S_];
__device__ float g_ker[B_ * N_ * N_];
__device__ float g_attn[R_ * E_];
__device__ float g_sin[N_ * 64];
__device__ float g_cos[N_ * 64];

// ---------------- smem stage layout (bytes) ----------------------------------
#define A_STRIDE 80            // 40 halfs per row (128 rows x 32 k)
#define BSTRIDE_NC 272         // 136 halfs per k-row (32 k x 128 n)
#define OFF_AL 10240
#define OFF_BH 20480
#define OFF_BL 30720
#define STAGE  40960
#define SMEMB  (2 * STAGE)

// ============================ PTX helpers ====================================
__device__ __forceinline__ uint32_t smem_u32(const void* p) {
    uint32_t a;
    asm("{ .reg .u64 t; cvta.to.shared.u64 t, %1; cvt.u32.u64 %0, t; }"
        : "=r"(a) : "l"(p));
    return a;
}
__device__ __forceinline__ void ldm4(uint32_t r[4], uint32_t a) {
    asm volatile("ldmatrix.sync.aligned.m8n8.x4.shared.b16 {%0,%1,%2,%3}, [%4];"
        : "=r"(r[0]), "=r"(r[1]), "=r"(r[2]), "=r"(r[3]) : "r"(a));
}
__device__ __forceinline__ void ldm2(uint32_t r[2], uint32_t a) {
    asm volatile("ldmatrix.sync.aligned.m8n8.x2.shared.b16 {%0,%1}, [%2];"
        : "=r"(r[0]), "=r"(r[1]) : "r"(a));
}
__device__ __forceinline__ void ldm2t(uint32_t r[2], uint32_t a) {
    asm volatile("ldmatrix.sync.aligned.m8n8.x2.trans.shared.b16 {%0,%1}, [%2];"
        : "=r"(r[0]), "=r"(r[1]) : "r"(a));
}
__device__ __forceinline__ void mma16816(float d[4], const uint32_t a[4],
                                         const uint32_t b[2]) {
    asm volatile(
        "mma.sync.aligned.m16n8k16.row.col.f32.bf16.bf16.f32 "
        "{%0,%1,%2,%3}, {%4,%5,%6,%7}, {%8,%9}, {%0,%1,%2,%3};"
        : "+f"(d[0]), "+f"(d[1]), "+f"(d[2]), "+f"(d[3])
        : "r"(a[0]), "r"(a[1]), "r"(a[2]), "r"(a[3]), "r"(b[0]), "r"(b[1]));
}

// ---------------- bf16 hi/lo split -------------------------------------------
__device__ __forceinline__ void split2(float a, float b, uint32_t& hi, uint32_t& lo) {
    __nv_bfloat16 ah = __float2bfloat16(a), bh = __float2bfloat16(b);
    __nv_bfloat16 al = __float2bfloat16(a - __bfloat162float(ah));
    __nv_bfloat16 bl = __float2bfloat16(b - __bfloat162float(bh));
    __nv_bfloat162 h; h.x = ah; h.y = bh;
    __nv_bfloat162 l; l.x = al; l.y = bl;
    hi = *reinterpret_cast<uint32_t*>(&h);
    lo = *reinterpret_cast<uint32_t*>(&l);
}

// ---------------- gmem->reg loaders and reg->smem split-stores ---------------
// K-contiguous: 128 rows x 32 k floats
__device__ __forceinline__ void load_kc4(float4 r[4], const float* __restrict__ src,
                                         int ld, int tid) {
    int rr = tid >> 3, kq = tid & 7;
    #pragma unroll
    for (int p = 0; p < 4; ++p)
        r[p] = *(const float4*)(src + (size_t)(p * 32 + rr) * ld + kq * 4);
}
__device__ __forceinline__ void store_kc4(char* hi, char* lo, const float4 r[4], int tid) {
    int rr = tid >> 3, kq = tid & 7;
    #pragma unroll
    for (int p = 0; p < 4; ++p) {
        int m = p * 32 + rr;
        uint32_t h0, l0, h1, l1;
        split2(r[p].x, r[p].y, h0, l0);
        split2(r[p].z, r[p].w, h1, l1);
        *(uint2*)(hi + m * A_STRIDE + kq * 8) = make_uint2(h0, h1);
        *(uint2*)(lo + m * A_STRIDE + kq * 8) = make_uint2(l0, l1);
    }
}
// N-contiguous: 32 k rows x 128 n floats  (stored [k][n] for ldmatrix.trans)
__device__ __forceinline__ void load_nc4(float4 r[4], const float* __restrict__ src,
                                         int ld, int tid) {
    int kk = tid >> 5, n = (tid & 31) * 4;
    #pragma unroll
    for (int p = 0; p < 4; ++p)
        r[p] = *(const float4*)(src + (size_t)(p * 8 + kk) * ld + n);
}
__device__ __forceinline__ void store_nc4(char* hi, char* lo, const float4 r[4], int tid) {
    int kk = tid >> 5, n8 = (tid & 31) * 8;
    #pragma unroll
    for (int p = 0; p < 4; ++p) {
        int k = p * 8 + kk;
        uint32_t h0, l0, h1, l1;
        split2(r[p].x, r[p].y, h0, l0);
        split2(r[p].z, r[p].w, h1, l1);
        *(uint2*)(hi + k * BSTRIDE_NC + n8) = make_uint2(h0, h1);
        *(uint2*)(lo + k * BSTRIDE_NC + n8) = make_uint2(l0, l1);
    }
}

// ---------------- generic bf16x3 mma.sync GEMM with fused epilogues ----------
// BNC: B operand is N-contiguous [K,N] (else K-contiguous [N,K])
// EPI: 0 = uv (bias+silu), 1 = scores (bias/mask/relu^2), 2 = attn (*u),
//      3 = out (+o_b + residual -> C)
template <int BNC, int EPI>
__global__ __launch_bounds__(256, 1)
void gau_gemm(const float* __restrict__ A, int lda, long long sAz,
              const float* __restrict__ Bp, int ldb, long long sBz,
              int K,
              const float* __restrict__ e0, const float* __restrict__ e1,
              float* __restrict__ C)
{
    extern __shared__ char sm[];
    const int tid = threadIdx.x, wid = tid >> 5, lane = tid & 31;
    const int z = blockIdx.z;

    A += (size_t)z * sAz + (size_t)blockIdx.y * 128 * lda;
    if (BNC) Bp += (size_t)z * sBz + blockIdx.x * 128;
    else     Bp += (size_t)z * sBz + (size_t)blockIdx.x * 128 * ldb;

    const int mb = (wid & 1) * 64;
    const int nb = (wid >> 1) * 32;

    float acc[4][4][4];
    #pragma unroll
    for (int i = 0; i < 4; ++i)
        #pragma unroll
        for (int j = 0; j < 4; ++j)
            #pragma unroll
            for (int q = 0; q < 4; ++q) acc[i][j][q] = 0.f;

    const int nch = K / 32;
    float4 ra[4], rb[4];
    load_kc4(ra, A, lda, tid);
    if (BNC) load_nc4(rb, Bp, ldb, tid);
    else     load_kc4(rb, Bp, ldb, tid);

    for (int c = 0; c < nch; ++c) {
        char* buf = sm + (c & 1) * STAGE;
        store_kc4(buf, buf + OFF_AL, ra, tid);
        if (BNC) store_nc4(buf + OFF_BH, buf + OFF_BL, rb, tid);
        else     store_kc4(buf + OFF_BH, buf + OFF_BL, rb, tid);
        __syncthreads();
        if (c + 1 < nch) {
            load_kc4(ra, A + (c + 1) * 32, lda, tid);
            if (BNC) load_nc4(rb, Bp + (size_t)(c + 1) * 32 * ldb, ldb, tid);
            else     load_kc4(rb, Bp + (c + 1) * 32, ldb, tid);
        }
        uint32_t sb = smem_u32(buf);
        #pragma unroll
        for (int ks = 0; ks < 2; ++ks) {
            uint32_t ah[4][4], al[4][4];
            #pragma unroll
            for (int mt = 0; mt < 4; ++mt) {
                uint32_t ad = sb + (mb + mt * 16 + (lane & 15)) * A_STRIDE
                            + ks * 32 + (lane >> 4) * 16;
                ldm4(ah[mt], ad);
                ldm4(al[mt], ad + OFF_AL);
            }
            uint32_t bh[4][2], bl[4][2];
            #pragma unroll
            for (int nt = 0; nt < 4; ++nt) {
                if (BNC) {
                    uint32_t bd = sb + OFF_BH + (ks * 16 + (lane & 15)) * BSTRIDE_NC
                                + (nb + nt * 8) * 2;
                    ldm2t(bh[nt], bd);
                    ldm2t(bl[nt], bd + (OFF_BL - OFF_BH));
                } else {
                    uint32_t bd = sb + OFF_BH + (nb + nt * 8 + (lane & 7)) * A_STRIDE
                                + ks * 32 + ((lane >> 3) & 1) * 16;
                    ldm2(bh[nt], bd);
                    ldm2(bl[nt], bd + (OFF_BL - OFF_BH));
                }
            }
            #pragma unroll
            for (int mt = 0; mt < 4; ++mt)
                #pragma unroll
                for (int nt = 0; nt < 4; ++nt) {
                    mma16816(acc[mt][nt], ah[mt], bh[nt]);
                    mma16816(acc[mt][nt], ah[mt], bl[nt]);
                    mma16816(acc[mt][nt], al[mt], bh[nt]);
                }
        }
        __syncthreads();
    }

    // ---------------- fused epilogue straight from fragments ----------------
    const int rbase = blockIdx.y * 128 + mb + (lane >> 2);
    const int cbase = blockIdx.x * 128 + nb + (lane & 3) * 2;
    #pragma unroll
    for (int mt = 0; mt < 4; ++mt) {
        #pragma unroll
        for (int hf = 0; hf < 2; ++hf) {
            int r = rbase + mt * 16 + hf * 8;       // row within this GEMM's M
            int grow = z * N_ + r;                  // global row (z=0 when unbatched)
            #pragma unroll
            for (int nt = 0; nt < 4; ++nt) {
                float v0 = acc[mt][nt][hf * 2 + 0];
                float v1 = acc[mt][nt][hf * 2 + 1];
                int cc = cbase + nt * 8;
                if (EPI == 0) {
                    v0 += e0[cc];     v1 += e0[cc + 1];
                    v0 = v0 / (1.f + expf(-v0));
                    v1 = v1 / (1.f + expf(-v1));
                    *(float2*)&g_uv[(size_t)grow * UVW + cc] = make_float2(v0, v1);
                } else if (EPI == 1) {
                    float m0 = (1.f - e1[z * N_ + cc])     * (-1e12f);
                    float m1 = (1.f - e1[z * N_ + cc + 1]) * (-1e12f);
                    float s0 = v0 * (1.f / MAXSEQ) + e0[cc - r + (MAXSEQ - 1)]     + m0;
                    float s1 = v1 * (1.f / MAXSEQ) + e0[cc + 1 - r + (MAXSEQ - 1)] + m1;
                    s0 = fmaxf(s0, 0.f); s1 = fmaxf(s1, 0.f);
                    *(float2*)&g_ker[((size_t)z * N_ + r) * N_ + cc] =
                        make_float2(s0 * s0, s1 * s1);
                } else if (EPI == 2) {
                    float2 u = *(const float2*)&g_uv[(size_t)grow * UVW + cc];
                    *(float2*)&g_attn[(size_t)grow * E_ + cc] =
                        make_float2(v0 * u.x, v1 * u.y);
                } else {
                    float2 xr = *(const float2*)&e1[(size_t)grow * H_ + cc];
                    *(float2*)&C[(size_t)grow * H_ + cc] =
                        make_float2(v0 + e0[cc] + xr.x, v1 + e0[cc + 1] + xr.y);
                }
            }
        }
    }
}

// ---------------- sin/cos table (replicates reference fp32 arithmetic) ------
__global__ void sincos_kernel() {
    int i = blockIdx.x * 256 + threadIdx.x;
    if (i >= N_ * 64) return;
    int d = i & 63;
    int pos = i >> 6;
    float invf = (float)pow(10000.0, (double)d * (1.0 / 64.0));
    float arg = (float)pos * invf;
    g_sin[i] = (float)sin((double)arg);
    g_cos[i] = (float)cos((double)arg);
}

// ---------------- LayerNorm --------------------------------------------------
__global__ __launch_bounds__(256) void ln_kernel(
    const float* __restrict__ x, const float* __restrict__ ln_g,
    const float* __restrict__ ln_b)
{
    int row = blockIdx.x;
    const float4* xr = (const float4*)(x + (size_t)row * H_);
    float4 v = xr[threadIdx.x];
    float s = v.x + v.y + v.z + v.w;
    float sq = v.x * v.x + v.y * v.y + v.z * v.z + v.w * v.w;
    #pragma unroll
    for (int o = 16; o; o >>= 1) {
        s  += __shfl_down_sync(0xffffffffu, s, o);
        sq += __shfl_down_sync(0xffffffffu, sq, o);
    }
    __shared__ float ss[8], ssq[8];
    int wrp = threadIdx.x >> 5, l = threadIdx.x & 31;
    if (l == 0) { ss[wrp] = s; ssq[wrp] = sq; }
    __syncthreads();
    if (wrp == 0) {
        s  = (l < 8) ? ss[l] : 0.f;
        sq = (l < 8) ? ssq[l] : 0.f;
        #pragma unroll
        for (int o = 4; o; o >>= 1) {
            s  += __shfl_down_sync(0xffu, s, o);
            sq += __shfl_down_sync(0xffu, sq, o);
        }
        if (l == 0) { ss[0] = s; ssq[0] = sq; }
    }
    __syncthreads();
    float mu = ss[0] * (1.f / H_);
    float var = ssq[0] * (1.f / H_) - mu * mu;
    float rs = rsqrtf(var + 1e-5f);
    float4 g = ((const float4*)ln_g)[threadIdx.x];
    float4 bb = ((const float4*)ln_b)[threadIdx.x];
    float4 o;
    o.x = (v.x - mu) * rs * g.x + bb.x;
    o.y = (v.y - mu) * rs * g.y + bb.y;
    o.z = (v.z - mu) * rs * g.z + bb.z;
    o.w = (v.w - mu) * rs * g.w + bb.w;
    ((float4*)(g_xn + (size_t)row * H_))[threadIdx.x] = o;
}

// ---------------- RoPE on base -> q, k ---------------------------------------
__global__ __launch_bounds__(128) void rope_kernel(
    const float* __restrict__ gamma, const float* __restrict__ beta)
{
    int row = blockIdx.x;
    int t = threadIdx.x;
    __shared__ float pq[128], pk[128];
    float base = g_uv[(size_t)row * UVW + 2 * E_ + t];
    pq[t] = base * gamma[t]       + beta[t];
    pk[t] = base * gamma[128 + t] + beta[128 + t];
    __syncthreads();
    int pos = row & (N_ - 1);
    if (t < 64) {
        float s = g_sin[pos * 64 + t], c = g_cos[pos * 64 + t];
        float x1 = pq[t], x2 = pq[t + 64];
        g_q[(size_t)row * S_ + t]      = x1 * c - x2 * s;
        g_q[(size_t)row * S_ + t + 64] = x2 * c + x1 * s;
    } else {
        int d = t - 64;
        float s = g_sin[pos * 64 + d], c = g_cos[pos * 64 + d];
        float x1 = pk[d], x2 = pk[d + 64];
        g_k[(size_t)row * S_ + d]      = x1 * c - x2 * s;
        g_k[(size_t)row * S_ + d + 64] = x2 * c + x1 * s;
    }
}

// ---------------- launch -----------------------------------------------------
extern "C" void kernel_launch(void* const* d_in, const int* in_sizes, int n_in,
                              void* d_out, int out_size)
{
    const float* x     = (const float*)d_in[0];
    const float* mask  = (const float*)d_in[1];
    const float* gamma = (const float*)d_in[2];
    const float* beta  = (const float*)d_in[3];
    const float* w     = (const float*)d_in[4];
    const float* uv_w  = (const float*)d_in[7];
    const float* uv_b  = (const float*)d_in[8];
    const float* o_w   = (const float*)d_in[9];
    const float* o_b   = (const float*)d_in[10];
    const float* ln_g  = (const float*)d_in[11];
    const float* ln_b  = (const float*)d_in[12];
    float* out = (float*)d_out;

    cudaFuncSetAttribute(gau_gemm<1, 0>, cudaFuncAttributeMaxDynamicSharedMemorySize, SMEMB);
    cudaFuncSetAttribute(gau_gemm<0, 1>, cudaFuncAttributeMaxDynamicSharedMemorySize, SMEMB);
    cudaFuncSetAttribute(gau_gemm<1, 2>, cudaFuncAttributeMaxDynamicSharedMemorySize, SMEMB);
    cudaFuncSetAttribute(gau_gemm<1, 3>, cudaFuncAttributeMaxDynamicSharedMemorySize, SMEMB);

    float *p_xn, *p_q, *p_k, *p_ker, *p_attn, *p_uv;
    cudaGetSymbolAddress((void**)&p_xn,  g_xn);
    cudaGetSymbolAddress((void**)&p_q,   g_q);
    cudaGetSymbolAddress((void**)&p_k,   g_k);
    cudaGetSymbolAddress((void**)&p_ker, g_ker);
    cudaGetSymbolAddress((void**)&p_attn,g_attn);
    cudaGetSymbolAddress((void**)&p_uv,  g_uv);

    sincos_kernel<<<128, 256>>>();
    ln_kernel<<<R_, 256>>>(x, ln_g, ln_b);

    // uv = silu(xn @ uv_w + uv_b)        [16384 x 4224 x 1024], B n-contig
    gau_gemm<1, 0><<<dim3(UVW / 128, R_ / 128, 1), 256, SMEMB>>>(
        p_xn, H_, 0LL, uv_w, UVW, 0LL, H_, uv_b, nullptr, nullptr);

    rope_kernel<<<R_, 128>>>(gamma, beta);

    // kernel = relu(q@k^T/512 + bias + mask)^2   [512 x 512 x 128] x32, B k-contig
    gau_gemm<0, 1><<<dim3(N_ / 128, N_ / 128, B_), 256, SMEMB>>>(
        p_q, S_, (long long)N_ * S_, p_k, S_, (long long)N_ * S_, S_, w, mask, nullptr);

    // attn = u * (kernel @ v)            [512 x 2048 x 512] x32, B n-contig
    gau_gemm<1, 2><<<dim3(E_ / 128, N_ / 128, B_), 256, SMEMB>>>(
        p_ker, N_, (long long)N_ * N_, p_uv + E_, UVW, (long long)N_ * UVW, N_,
        nullptr, nullptr, nullptr);

    // out = attn @ o_w + o_b + x         [16384 x 1024 x 2048], B n-contig
    gau_gemm<1, 3><<<dim3(H_ / 128, R_ / 128, 1), 256, SMEMB>>>(
        p_attn, E_, 0LL, o_w, H_, 0LL, E_, o_b, x, out);
}

// round 5
// speedup vs baseline: 2.2018x; 1.0553x over previous
#include <cuda_runtime.h>
#include <cuda_bf16.h>
#include <cstdint>
#include <math.h>

// Problem constants
#define B_  32
#define N_  512
#define H_  1024
#define E_  2048
#define S_  128
#define R_  (B_ * N_)          // 16384 rows
#define UVW (2 * E_ + S_)      // 4224
#define MAXSEQ 512

// ---------------- scratch (device globals; no allocations allowed) ----------
__device__ float g_xn[R_ * H_];
__device__ float g_uv[R_ * UVW];
__device__ float g_q[R_ * S_];
__device__ float g_k[R_ * S_];
__device__ float g_ker[B_ * N_ * N_];
__device__ float g_attn[R_ * E_];
__device__ float g_sin[N_ * 64];
__device__ float g_cos[N_ * 64];

// ---------------- smem stage layout (bytes) ----------------------------------
#define A_STRIDE 80            // 40 halfs per row (128 rows x 32 k)
#define BSTRIDE_NC 272         // 136 halfs per k-row (32 k x 128 n)
#define OFF_AL 10240
#define OFF_BH 20480
#define OFF_BL 30720
#define STAGE  40960
#define SMEMB  (2 * STAGE)

// ============================ PTX helpers ====================================
__device__ __forceinline__ uint32_t smem_u32(const void* p) {
    uint32_t a;
    asm("{ .reg .u64 t; cvta.to.shared.u64 t, %1; cvt.u32.u64 %0, t; }"
        : "=r"(a) : "l"(p));
    return a;
}
__device__ __forceinline__ void ldm4(uint32_t r[4], uint32_t a) {
    asm volatile("ldmatrix.sync.aligned.m8n8.x4.shared.b16 {%0,%1,%2,%3}, [%4];"
        : "=r"(r[0]), "=r"(r[1]), "=r"(r[2]), "=r"(r[3]) : "r"(a));
}
__device__ __forceinline__ void ldm2(uint32_t r[2], uint32_t a) {
    asm volatile("ldmatrix.sync.aligned.m8n8.x2.shared.b16 {%0,%1}, [%2];"
        : "=r"(r[0]), "=r"(r[1]) : "r"(a));
}
__device__ __forceinline__ void ldm2t(uint32_t r[2], uint32_t a) {
    asm volatile("ldmatrix.sync.aligned.m8n8.x2.trans.shared.b16 {%0,%1}, [%2];"
        : "=r"(r[0]), "=r"(r[1]) : "r"(a));
}
__device__ __forceinline__ void mma16816(float d[4], const uint32_t a[4],
                                         const uint32_t b[2]) {
    asm volatile(
        "mma.sync.aligned.m16n8k16.row.col.f32.bf16.bf16.f32 "
        "{%0,%1,%2,%3}, {%4,%5,%6,%7}, {%8,%9}, {%0,%1,%2,%3};"
        : "+f"(d[0]), "+f"(d[1]), "+f"(d[2]), "+f"(d[3])
        : "r"(a[0]), "r"(a[1]), "r"(a[2]), "r"(a[3]), "r"(b[0]), "r"(b[1]));
}

// ---------------- bf16 hi/lo split -------------------------------------------
__device__ __forceinline__ void split2(float a, float b, uint32_t& hi, uint32_t& lo) {
    __nv_bfloat16 ah = __float2bfloat16(a), bh = __float2bfloat16(b);
    __nv_bfloat16 al = __float2bfloat16(a - __bfloat162float(ah));
    __nv_bfloat16 bl = __float2bfloat16(b - __bfloat162float(bh));
    __nv_bfloat162 h; h.x = ah; h.y = bh;
    __nv_bfloat162 l; l.x = al; l.y = bl;
    hi = *reinterpret_cast<uint32_t*>(&h);
    lo = *reinterpret_cast<uint32_t*>(&l);
}

// ---------------- gmem->reg loaders and reg->smem split-stores (512 thr) -----
// K-contiguous: 128 rows x 32 k floats (2 float4 / thread)
__device__ __forceinline__ void load_kc(float4 r[2], const float* __restrict__ src,
                                        int ld, int tid) {
    int rr = tid >> 2;
    #pragma unroll
    for (int p = 0; p < 2; ++p)
        r[p] = *(const float4*)(src + (size_t)rr * ld + ((tid & 3) + p * 4) * 4);
}
__device__ __forceinline__ void store_kc(char* hi, char* lo, const float4 r[2], int tid) {
    int rr = tid >> 2;
    #pragma unroll
    for (int p = 0; p < 2; ++p) {
        int kq = (tid & 3) + p * 4;
        uint32_t h0, l0, h1, l1;
        split2(r[p].x, r[p].y, h0, l0);
        split2(r[p].z, r[p].w, h1, l1);
        *(uint2*)(hi + rr * A_STRIDE + kq * 8) = make_uint2(h0, h1);
        *(uint2*)(lo + rr * A_STRIDE + kq * 8) = make_uint2(l0, l1);
    }
}
// N-contiguous: 32 k rows x 128 n floats, stored [k][n] for ldmatrix.trans
__device__ __forceinline__ void load_nc(float4 r[2], const float* __restrict__ src,
                                        int ld, int tid) {
    int kk = tid >> 4;
    #pragma unroll
    for (int p = 0; p < 2; ++p)
        r[p] = *(const float4*)(src + (size_t)kk * ld + ((tid & 15) + p * 16) * 4);
}
__device__ __forceinline__ void store_nc(char* hi, char* lo, const float4 r[2], int tid) {
    int kk = tid >> 4;
    #pragma unroll
    for (int p = 0; p < 2; ++p) {
        int n8 = ((tid & 15) + p * 16) * 8;
        uint32_t h0, l0, h1, l1;
        split2(r[p].x, r[p].y, h0, l0);
        split2(r[p].z, r[p].w, h1, l1);
        *(uint2*)(hi + kk * BSTRIDE_NC + n8) = make_uint2(h0, h1);
        *(uint2*)(lo + kk * BSTRIDE_NC + n8) = make_uint2(l0, l1);
    }
}

// ---------------- generic bf16x3 mma.sync GEMM with fused epilogues ----------
// 128x128 CTA tile, 512 threads, 16 warps of 32x32 each.
// BNC: B operand is N-contiguous [K,N] (else K-contiguous [N,K])
// EPI: 0 = uv (bias+silu), 1 = scores (bias/mask/relu^2), 2 = attn (*u),
//      3 = out (+o_b + residual -> C)
template <int BNC, int EPI>
__global__ __launch_bounds__(512, 1)
void gau_gemm(const float* __restrict__ A, int lda, long long sAz,
              const float* __restrict__ Bp, int ldb, long long sBz,
              int K,
              const float* __restrict__ e0, const float* __restrict__ e1,
              float* __restrict__ C)
{
    extern __shared__ char sm[];
    const int tid = threadIdx.x, wid = tid >> 5, lane = tid & 31;
    const int z = blockIdx.z;

    A += (size_t)z * sAz + (size_t)blockIdx.y * 128 * lda;
    if (BNC) Bp += (size_t)z * sBz + blockIdx.x * 128;
    else     Bp += (size_t)z * sBz + (size_t)blockIdx.x * 128 * ldb;

    const int mb = (wid & 3) * 32;
    const int nb = (wid >> 2) * 32;

    float acc[2][4][4];
    #pragma unroll
    for (int i = 0; i < 2; ++i)
        #pragma unroll
        for (int j = 0; j < 4; ++j)
            #pragma unroll
            for (int q = 0; q < 4; ++q) acc[i][j][q] = 0.f;

    const int nch = K / 32;
    float4 ra[2], rb[2];
    load_kc(ra, A, lda, tid);
    if (BNC) load_nc(rb, Bp, ldb, tid);
    else     load_kc(rb, Bp, ldb, tid);

    for (int c = 0; c < nch; ++c) {
        char* buf = sm + (c & 1) * STAGE;
        store_kc(buf, buf + OFF_AL, ra, tid);
        if (BNC) store_nc(buf + OFF_BH, buf + OFF_BL, rb, tid);
        else     store_kc(buf + OFF_BH, buf + OFF_BL, rb, tid);
        __syncthreads();
        if (c + 1 < nch) {
            load_kc(ra, A + (c + 1) * 32, lda, tid);
            if (BNC) load_nc(rb, Bp + (size_t)(c + 1) * 32 * ldb, ldb, tid);
            else     load_kc(rb, Bp + (c + 1) * 32, ldb, tid);
        }
        uint32_t sb = smem_u32(buf);
        #pragma unroll
        for (int ks = 0; ks < 2; ++ks) {
            uint32_t ah[2][4], al[2][4];
            #pragma unroll
            for (int mt = 0; mt < 2; ++mt) {
                uint32_t ad = sb + (mb + mt * 16 + (lane & 15)) * A_STRIDE
                            + ks * 32 + (lane >> 4) * 16;
                ldm4(ah[mt], ad);
                ldm4(al[mt], ad + OFF_AL);
            }
            uint32_t bh[4][2], bl[4][2];
            #pragma unroll
            for (int nt = 0; nt < 4; ++nt) {
                if (BNC) {
                    uint32_t bd = sb + OFF_BH + (ks * 16 + (lane & 15)) * BSTRIDE_NC
                                + (nb + nt * 8) * 2;
                    ldm2t(bh[nt], bd);
                    ldm2t(bl[nt], bd + (OFF_BL - OFF_BH));
                } else {
                    uint32_t bd = sb + OFF_BH + (nb + nt * 8 + (lane & 7)) * A_STRIDE
                                + ks * 32 + ((lane >> 3) & 1) * 16;
                    ldm2(bh[nt], bd);
                    ldm2(bl[nt], bd + (OFF_BL - OFF_BH));
                }
            }
            #pragma unroll
            for (int mt = 0; mt < 2; ++mt)
                #pragma unroll
                for (int nt = 0; nt < 4; ++nt) {
                    mma16816(acc[mt][nt], ah[mt], bh[nt]);
                    mma16816(acc[mt][nt], ah[mt], bl[nt]);
                    mma16816(acc[mt][nt], al[mt], bh[nt]);
                }
        }
        // single barrier per chunk is sufficient with double buffering:
        // stores of chunk c+2 (same buffer) can only start after all warps
        // passed the post-store barrier of chunk c+1, which implies mma(c) done.
    }

    // ---------------- fused epilogue straight from fragments ----------------
    const int rbase = blockIdx.y * 128 + mb + (lane >> 2);
    const int cbase = blockIdx.x * 128 + nb + (lane & 3) * 2;
    #pragma unroll
    for (int mt = 0; mt < 2; ++mt) {
        #pragma unroll
        for (int hf = 0; hf < 2; ++hf) {
            int r = rbase + mt * 16 + hf * 8;       // row within this GEMM's M
            int grow = z * N_ + r;                  // global row (z=0 when unbatched)
            #pragma unroll
            for (int nt = 0; nt < 4; ++nt) {
                float v0 = acc[mt][nt][hf * 2 + 0];
                float v1 = acc[mt][nt][hf * 2 + 1];
                int cc = cbase + nt * 8;
                if (EPI == 0) {
                    v0 += e0[cc];     v1 += e0[cc + 1];
                    v0 = v0 / (1.f + expf(-v0));
                    v1 = v1 / (1.f + expf(-v1));
                    *(float2*)&g_uv[(size_t)grow * UVW + cc] = make_float2(v0, v1);
                } else if (EPI == 1) {
                    float m0 = (1.f - e1[z * N_ + cc])     * (-1e12f);
                    float m1 = (1.f - e1[z * N_ + cc + 1]) * (-1e12f);
                    float s0 = v0 * (1.f / MAXSEQ) + e0[cc - r + (MAXSEQ - 1)]     + m0;
                    float s1 = v1 * (1.f / MAXSEQ) + e0[cc + 1 - r + (MAXSEQ - 1)] + m1;
                    s0 = fmaxf(s0, 0.f); s1 = fmaxf(s1, 0.f);
                    *(float2*)&g_ker[((size_t)z * N_ + r) * N_ + cc] =
                        make_float2(s0 * s0, s1 * s1);
                } else if (EPI == 2) {
                    float2 u = *(const float2*)&g_uv[(size_t)grow * UVW + cc];
                    *(float2*)&g_attn[(size_t)grow * E_ + cc] =
                        make_float2(v0 * u.x, v1 * u.y);
                } else {
                    float2 xr = *(const float2*)&e1[(size_t)grow * H_ + cc];
                    *(float2*)&C[(size_t)grow * H_ + cc] =
                        make_float2(v0 + e0[cc] + xr.x, v1 + e0[cc + 1] + xr.y);
                }
            }
        }
    }
}

// ---------------- sin/cos table (replicates reference fp32 arithmetic) ------
__global__ void sincos_kernel() {
    int i = blockIdx.x * 256 + threadIdx.x;
    if (i >= N_ * 64) return;
    int d = i & 63;
    int pos = i >> 6;
    float invf = (float)pow(10000.0, (double)d * (1.0 / 64.0));
    float arg = (float)pos * invf;
    g_sin[i] = (float)sin((double)arg);
    g_cos[i] = (float)cos((double)arg);
}

// ---------------- LayerNorm --------------------------------------------------
__global__ __launch_bounds__(256) void ln_kernel(
    const float* __restrict__ x, const float* __restrict__ ln_g,
    const float* __restrict__ ln_b)
{
    int row = blockIdx.x;
    const float4* xr = (const float4*)(x + (size_t)row * H_);
    float4 v = xr[threadIdx.x];
    float s = v.x + v.y + v.z + v.w;
    float sq = v.x * v.x + v.y * v.y + v.z * v.z + v.w * v.w;
    #pragma unroll
    for (int o = 16; o; o >>= 1) {
        s  += __shfl_down_sync(0xffffffffu, s, o);
        sq += __shfl_down_sync(0xffffffffu, sq, o);
    }
    __shared__ float ss[8], ssq[8];
    int wrp = threadIdx.x >> 5, l = threadIdx.x & 31;
    if (l == 0) { ss[wrp] = s; ssq[wrp] = sq; }
    __syncthreads();
    if (wrp == 0) {
        s  = (l < 8) ? ss[l] : 0.f;
        sq = (l < 8) ? ssq[l] : 0.f;
        #pragma unroll
        for (int o = 4; o; o >>= 1) {
            s  += __shfl_down_sync(0xffu, s, o);
            sq += __shfl_down_sync(0xffu, sq, o);
        }
        if (l == 0) { ss[0] = s; ssq[0] = sq; }
    }
    __syncthreads();
    float mu = ss[0] * (1.f / H_);
    float var = ssq[0] * (1.f / H_) - mu * mu;
    float rs = rsqrtf(var + 1e-5f);
    float4 g = ((const float4*)ln_g)[threadIdx.x];
    float4 bb = ((const float4*)ln_b)[threadIdx.x];
    float4 o;
    o.x = (v.x - mu) * rs * g.x + bb.x;
    o.y = (v.y - mu) * rs * g.y + bb.y;
    o.z = (v.z - mu) * rs * g.z + bb.z;
    o.w = (v.w - mu) * rs * g.w + bb.w;
    ((float4*)(g_xn + (size_t)row * H_))[threadIdx.x] = o;
}

// ---------------- RoPE on base -> q, k ---------------------------------------
__global__ __launch_bounds__(128) void rope_kernel(
    const float* __restrict__ gamma, const float* __restrict__ beta)
{
    int row = blockIdx.x;
    int t = threadIdx.x;
    __shared__ float pq[128], pk[128];
    float base = g_uv[(size_t)row * UVW + 2 * E_ + t];
    pq[t] = base * gamma[t]       + beta[t];
    pk[t] = base * gamma[128 + t] + beta[128 + t];
    __syncthreads();
    int pos = row & (N_ - 1);
    if (t < 64) {
        float s = g_sin[pos * 64 + t], c = g_cos[pos * 64 + t];
        float x1 = pq[t], x2 = pq[t + 64];
        g_q[(size_t)row * S_ + t]      = x1 * c - x2 * s;
        g_q[(size_t)row * S_ + t + 64] = x2 * c + x1 * s;
    } else {
        int d = t - 64;
        float s = g_sin[pos * 64 + d], c = g_cos[pos * 64 + d];
        float x1 = pk[d], x2 = pk[d + 64];
        g_k[(size_t)row * S_ + d]      = x1 * c - x2 * s;
        g_k[(size_t)row * S_ + d + 64] = x2 * c + x1 * s;
    }
}

// ---------------- launch -----------------------------------------------------
extern "C" void kernel_launch(void* const* d_in, const int* in_sizes, int n_in,
                              void* d_out, int out_size)
{
    const float* x     = (const float*)d_in[0];
    const float* mask  = (const float*)d_in[1];
    const float* gamma = (const float*)d_in[2];
    const float* beta  = (const float*)d_in[3];
    const float* w     = (const float*)d_in[4];
    const float* uv_w  = (const float*)d_in[7];
    const float* uv_b  = (const float*)d_in[8];
    const float* o_w   = (const float*)d_in[9];
    const float* o_b   = (const float*)d_in[10];
    const float* ln_g  = (const float*)d_in[11];
    const float* ln_b  = (const float*)d_in[12];
    float* out = (float*)d_out;

    cudaFuncSetAttribute(gau_gemm<1, 0>, cudaFuncAttributeMaxDynamicSharedMemorySize, SMEMB);
    cudaFuncSetAttribute(gau_gemm<0, 1>, cudaFuncAttributeMaxDynamicSharedMemorySize, SMEMB);
    cudaFuncSetAttribute(gau_gemm<1, 2>, cudaFuncAttributeMaxDynamicSharedMemorySize, SMEMB);
    cudaFuncSetAttribute(gau_gemm<1, 3>, cudaFuncAttributeMaxDynamicSharedMemorySize, SMEMB);

    float *p_xn, *p_q, *p_k, *p_ker, *p_attn, *p_uv;
    cudaGetSymbolAddress((void**)&p_xn,  g_xn);
    cudaGetSymbolAddress((void**)&p_q,   g_q);
    cudaGetSymbolAddress((void**)&p_k,   g_k);
    cudaGetSymbolAddress((void**)&p_ker, g_ker);
    cudaGetSymbolAddress((void**)&p_attn,g_attn);
    cudaGetSymbolAddress((void**)&p_uv,  g_uv);

    sincos_kernel<<<128, 256>>>();
    ln_kernel<<<R_, 256>>>(x, ln_g, ln_b);

    // uv = silu(xn @ uv_w + uv_b)        [16384 x 4224 x 1024], B n-contig
    gau_gemm<1, 0><<<dim3(UVW / 128, R_ / 128, 1), 512, SMEMB>>>(
        p_xn, H_, 0LL, uv_w, UVW, 0LL, H_, uv_b, nullptr, nullptr);

    rope_kernel<<<R_, 128>>>(gamma, beta);

    // kernel = relu(q@k^T/512 + bias + mask)^2   [512 x 512 x 128] x32, B k-contig
    gau_gemm<0, 1><<<dim3(N_ / 128, N_ / 128, B_), 512, SMEMB>>>(
        p_q, S_, (long long)N_ * S_, p_k, S_, (long long)N_ * S_, S_, w, mask, nullptr);

    // attn = u * (kernel @ v)            [512 x 2048 x 512] x32, B n-contig
    gau_gemm<1, 2><<<dim3(E_ / 128, N_ / 128, B_), 512, SMEMB>>>(
        p_ker, N_, (long long)N_ * N_, p_uv + E_, UVW, (long long)N_ * UVW, N_,
        nullptr, nullptr, nullptr);

    // out = attn @ o_w + o_b + x         [16384 x 1024 x 2048], B n-contig
    gau_gemm<1, 3><<<dim3(H_ / 128, R_ / 128, 1), 512, SMEMB>>>(
        p_attn, E_, 0LL, o_w, H_, 0LL, E_, o_b, x, out);
}

// round 6
// speedup vs baseline: 2.3510x; 1.0678x over previous
#include <cuda_runtime.h>
#include <cuda_bf16.h>
#include <cstdint>
#include <math.h>

// Problem constants
#define B_  32
#define N_  512
#define H_  1024
#define E_  2048
#define S_  128
#define R_  (B_ * N_)          // 16384 rows
#define UVW (2 * E_ + S_)      // 4224
#define MAXSEQ 512

// ---------------- scratch (device globals; no allocations allowed) ----------
// All GEMM operands are stored pre-split as bf16 (hi, lo) pairs.
__device__ __align__(16) __nv_bfloat16 g_xh[R_ * H_], g_xl[R_ * H_];       // LN out
__device__ __align__(16) __nv_bfloat16 g_wuh[H_ * UVW], g_wul[H_ * UVW];   // uv_w
__device__ __align__(16) __nv_bfloat16 g_woh[E_ * H_], g_wol[E_ * H_];     // o_w
__device__ __align__(16) float         g_u[R_ * E_];                       // gate (fp32)
__device__ __align__(16) __nv_bfloat16 g_vh[R_ * E_], g_vl[R_ * E_];       // v
__device__ __align__(16) float         g_base[R_ * S_];                    // pre-RoPE base
__device__ __align__(16) __nv_bfloat16 g_qh[R_ * S_], g_ql[R_ * S_];
__device__ __align__(16) __nv_bfloat16 g_kh[R_ * S_], g_kl[R_ * S_];
__device__ __align__(16) __nv_bfloat16 g_kerh[B_ * N_ * N_], g_kerl[B_ * N_ * N_];
__device__ __align__(16) __nv_bfloat16 g_ah[R_ * E_], g_al[R_ * E_];       // gated attn
__device__ float g_sin[N_ * 64];
__device__ float g_cos[N_ * 64];

// ---------------- smem stage layout (bytes) ----------------------------------
#define A_STRIDE 80            // 40 halfs per row (128 rows x 32 k), conflict-free
#define BSTRIDE_NC 272         // 136 halfs per k-row (32 k x 128 n), conflict-free
#define OFF_AL 10240
#define OFF_BH 20480
#define OFF_BL 30720
#define STAGE  40960
#define NSTG   4
#define SMEMB  (NSTG * STAGE)  // 160 KB

// ============================ PTX helpers ====================================
__device__ __forceinline__ uint32_t smem_u32(const void* p) {
    uint32_t a;
    asm("{ .reg .u64 t; cvta.to.shared.u64 t, %1; cvt.u32.u64 %0, t; }"
        : "=r"(a) : "l"(p));
    return a;
}
__device__ __forceinline__ void cpa16(uint32_t dst, const void* src) {
    asm volatile("cp.async.cg.shared.global [%0], [%1], 16;"
                 :: "r"(dst), "l"(src) : "memory");
}
#define CP_COMMIT() asm volatile("cp.async.commit_group;" ::: "memory")
#define CP_WAIT2()  asm volatile("cp.async.wait_group 2;" ::: "memory")

__device__ __forceinline__ void ldm4(uint32_t r[4], uint32_t a) {
    asm volatile("ldmatrix.sync.aligned.m8n8.x4.shared.b16 {%0,%1,%2,%3}, [%4];"
        : "=r"(r[0]), "=r"(r[1]), "=r"(r[2]), "=r"(r[3]) : "r"(a));
}
__device__ __forceinline__ void ldm4t(uint32_t r[4], uint32_t a) {
    asm volatile("ldmatrix.sync.aligned.m8n8.x4.trans.shared.b16 {%0,%1,%2,%3}, [%4];"
        : "=r"(r[0]), "=r"(r[1]), "=r"(r[2]), "=r"(r[3]) : "r"(a));
}
__device__ __forceinline__ void mma16816(float d[4], const uint32_t a[4],
                                         const uint32_t b[2]) {
    asm volatile(
        "mma.sync.aligned.m16n8k16.row.col.f32.bf16.bf16.f32 "
        "{%0,%1,%2,%3}, {%4,%5,%6,%7}, {%8,%9}, {%0,%1,%2,%3};"
        : "+f"(d[0]), "+f"(d[1]), "+f"(d[2]), "+f"(d[3])
        : "r"(a[0]), "r"(a[1]), "r"(a[2]), "r"(a[3]), "r"(b[0]), "r"(b[1]));
}

// ---------------- bf16 hi/lo split -------------------------------------------
__device__ __forceinline__ void split2(float a, float b, uint32_t& hi, uint32_t& lo) {
    __nv_bfloat16 ah = __float2bfloat16(a), bh = __float2bfloat16(b);
    __nv_bfloat16 al = __float2bfloat16(a - __bfloat162float(ah));
    __nv_bfloat16 bl = __float2bfloat16(b - __bfloat162float(bh));
    __nv_bfloat162 h; h.x = ah; h.y = bh;
    __nv_bfloat162 l; l.x = al; l.y = bl;
    hi = *reinterpret_cast<uint32_t*>(&h);
    lo = *reinterpret_cast<uint32_t*>(&l);
}

// ---------------- generic bf16x3 mma.sync GEMM with fused epilogues ----------
// 128x128 CTA tile, 512 threads, 16 warps (4x4 grid) of 32x32 warp tiles.
// Operands are pre-split bf16 hi/lo; main loop = cp.async + ldmatrix + HMMA.
// BNC: B operand is N-contiguous [K,N] (else K-contiguous [N,K])
// EPI: 0 = uv (bias+silu -> u | vh/vl | base), 1 = scores (-> kerh/kerl),
//      2 = attn (*u -> ah/al), 3 = out (+o_b + residual -> C)
template <int BNC, int EPI>
__global__ __launch_bounds__(512, 1)
void gau_gemm(const __nv_bfloat16* __restrict__ Ah, const __nv_bfloat16* __restrict__ Al,
              int lda, long long sAz,
              const __nv_bfloat16* __restrict__ Bh, const __nv_bfloat16* __restrict__ Bl,
              int ldb, long long sBz,
              int K,
              const float* __restrict__ e0, const float* __restrict__ e1,
              float* __restrict__ C)
{
    extern __shared__ char sm[];
    const int tid = threadIdx.x, wid = tid >> 5, lane = tid & 31;
    const int z = blockIdx.z;

    Ah += (size_t)z * sAz + (size_t)blockIdx.y * 128 * lda;
    Al += (size_t)z * sAz + (size_t)blockIdx.y * 128 * lda;
    if (BNC) { Bh += (size_t)z * sBz + blockIdx.x * 128;
               Bl += (size_t)z * sBz + blockIdx.x * 128; }
    else     { Bh += (size_t)z * sBz + (size_t)blockIdx.x * 128 * ldb;
               Bl += (size_t)z * sBz + (size_t)blockIdx.x * 128 * ldb; }

    const uint32_t sbase = smem_u32(sm);
    const int mb = (wid & 3) * 32;
    const int nb = (wid >> 2) * 32;

    // cp.async thread mappings (computed once)
    const int ar = tid >> 2,  ag = tid & 3;    // A/B-kc granule: row, 16B col
    const int bk = tid >> 4,  bg = tid & 15;   // B-nc granule: k-row, 16B col

    float acc[2][4][4];
    #pragma unroll
    for (int i = 0; i < 2; ++i)
        #pragma unroll
        for (int j = 0; j < 4; ++j)
            #pragma unroll
            for (int q = 0; q < 4; ++q) acc[i][j][q] = 0.f;

    const int nch = K / 32;

    auto issue = [&](int c) {
        uint32_t sb = sbase + (c & (NSTG - 1)) * STAGE;
        uint32_t da = sb + ar * A_STRIDE + ag * 16;
        cpa16(da,           Ah + (size_t)ar * lda + c * 32 + ag * 8);
        cpa16(da + OFF_AL,  Al + (size_t)ar * lda + c * 32 + ag * 8);
        if (BNC) {
            uint32_t db = sb + OFF_BH + bk * BSTRIDE_NC + bg * 16;
            cpa16(db,                     Bh + (size_t)(c * 32 + bk) * ldb + bg * 8);
            cpa16(db + (OFF_BL - OFF_BH), Bl + (size_t)(c * 32 + bk) * ldb + bg * 8);
        } else {
            uint32_t db = sb + OFF_BH + ar * A_STRIDE + ag * 16;
            cpa16(db,                     Bh + (size_t)ar * ldb + c * 32 + ag * 8);
            cpa16(db + (OFF_BL - OFF_BH), Bl + (size_t)ar * ldb + c * 32 + ag * 8);
        }
        CP_COMMIT();
    };

    issue(0); issue(1); issue(2);

    for (int c = 0; c < nch; ++c) {
        CP_WAIT2();
        __syncthreads();
        if (c + 3 < nch) issue(c + 3);

        uint32_t sb = sbase + (c & (NSTG - 1)) * STAGE;
        #pragma unroll
        for (int ks = 0; ks < 2; ++ks) {
            uint32_t ah[2][4], al[2][4];
            #pragma unroll
            for (int mt = 0; mt < 2; ++mt) {
                uint32_t ad = sb + (mb + mt * 16 + (lane & 15)) * A_STRIDE
                            + ks * 32 + (lane >> 4) * 16;
                ldm4(ah[mt], ad);
                ldm4(al[mt], ad + OFF_AL);
            }
            uint32_t bh[4][2], bl[4][2];
            #pragma unroll
            for (int np = 0; np < 2; ++np) {     // each x4 covers two n8 groups
                uint32_t r[4];
                if (BNC) {
                    uint32_t bd = sb + OFF_BH
                                + (ks * 16 + (lane & 15)) * BSTRIDE_NC
                                + (nb + np * 16 + (lane >> 4) * 8) * 2;
                    ldm4t(r, bd);
                    bh[np*2][0]=r[0]; bh[np*2][1]=r[1]; bh[np*2+1][0]=r[2]; bh[np*2+1][1]=r[3];
                    ldm4t(r, bd + (OFF_BL - OFF_BH));
                    bl[np*2][0]=r[0]; bl[np*2][1]=r[1]; bl[np*2+1][0]=r[2]; bl[np*2+1][1]=r[3];
                } else {
                    uint32_t bd = sb + OFF_BH
                                + (nb + np * 16 + (lane >> 4) * 8 + (lane & 7)) * A_STRIDE
                                + ks * 32 + ((lane >> 3) & 1) * 16;
                    ldm4(r, bd);
                    bh[np*2][0]=r[0]; bh[np*2][1]=r[1]; bh[np*2+1][0]=r[2]; bh[np*2+1][1]=r[3];
                    ldm4(r, bd + (OFF_BL - OFF_BH));
                    bl[np*2][0]=r[0]; bl[np*2][1]=r[1]; bl[np*2+1][0]=r[2]; bl[np*2+1][1]=r[3];
                }
            }
            #pragma unroll
            for (int mt = 0; mt < 2; ++mt)
                #pragma unroll
                for (int nt = 0; nt < 4; ++nt) {
                    mma16816(acc[mt][nt], ah[mt], bh[nt]);
                    mma16816(acc[mt][nt], ah[mt], bl[nt]);
                    mma16816(acc[mt][nt], al[mt], bh[nt]);
                }
        }
    }

    // ---------------- fused epilogue straight from fragments ----------------
    const int rbase = blockIdx.y * 128 + mb + (lane >> 2);
    const int cbase = blockIdx.x * 128 + nb + (lane & 3) * 2;
    const int xb = blockIdx.x;
    #pragma unroll
    for (int mt = 0; mt < 2; ++mt) {
        #pragma unroll
        for (int hf = 0; hf < 2; ++hf) {
            int r = rbase + mt * 16 + hf * 8;
            int grow = z * N_ + r;                  // global row (z=0 when unbatched)
            #pragma unroll
            for (int nt = 0; nt < 4; ++nt) {
                float v0 = acc[mt][nt][hf * 2 + 0];
                float v1 = acc[mt][nt][hf * 2 + 1];
                int cc = cbase + nt * 8;
                if (EPI == 0) {
                    v0 += e0[cc];     v1 += e0[cc + 1];
                    v0 = v0 / (1.f + expf(-v0));
                    v1 = v1 / (1.f + expf(-v1));
                    if (xb < 16) {
                        *(float2*)&g_u[(size_t)grow * E_ + cc] = make_float2(v0, v1);
                    } else if (xb < 32) {
                        uint32_t h, l; split2(v0, v1, h, l);
                        size_t idx = (size_t)grow * E_ + (cc - E_);
                        *(uint32_t*)&g_vh[idx] = h;
                        *(uint32_t*)&g_vl[idx] = l;
                    } else {
                        *(float2*)&g_base[(size_t)grow * S_ + (cc - 2 * E_)] =
                            make_float2(v0, v1);
                    }
                } else if (EPI == 1) {
                    float m0 = (1.f - e1[z * N_ + cc])     * (-1e12f);
                    float m1 = (1.f - e1[z * N_ + cc + 1]) * (-1e12f);
                    float s0 = v0 * (1.f / MAXSEQ) + e0[cc - r + (MAXSEQ - 1)]     + m0;
                    float s1 = v1 * (1.f / MAXSEQ) + e0[cc + 1 - r + (MAXSEQ - 1)] + m1;
                    s0 = fmaxf(s0, 0.f); s1 = fmaxf(s1, 0.f);
                    uint32_t h, l; split2(s0 * s0, s1 * s1, h, l);
                    size_t idx = ((size_t)z * N_ + r) * N_ + cc;
                    *(uint32_t*)&g_kerh[idx] = h;
                    *(uint32_t*)&g_kerl[idx] = l;
                } else if (EPI == 2) {
                    float2 u = *(const float2*)&g_u[(size_t)grow * E_ + cc];
                    uint32_t h, l; split2(v0 * u.x, v1 * u.y, h, l);
                    size_t idx = (size_t)grow * E_ + cc;
                    *(uint32_t*)&g_ah[idx] = h;
                    *(uint32_t*)&g_al[idx] = l;
                } else {
                    float2 xr = *(const float2*)&e1[(size_t)grow * H_ + cc];
                    *(float2*)&C[(size_t)grow * H_ + cc] =
                        make_float2(v0 + e0[cc] + xr.x, v1 + e0[cc + 1] + xr.y);
                }
            }
        }
    }
}

// ---------------- one-time fp32 -> bf16 hi/lo weight split -------------------
__global__ void split_kernel(const float* __restrict__ src,
                             __nv_bfloat16* __restrict__ h,
                             __nv_bfloat16* __restrict__ l, int n2) {
    int i = blockIdx.x * 256 + threadIdx.x;
    if (i >= n2) return;
    float2 v = ((const float2*)src)[i];
    uint32_t hi, lo; split2(v.x, v.y, hi, lo);
    ((uint32_t*)h)[i] = hi;
    ((uint32_t*)l)[i] = lo;
}

// ---------------- sin/cos table (replicates reference fp32 arithmetic) ------
__global__ void sincos_kernel() {
    int i = blockIdx.x * 256 + threadIdx.x;
    if (i >= N_ * 64) return;
    int d = i & 63;
    int pos = i >> 6;
    float invf = (float)pow(10000.0, (double)d * (1.0 / 64.0));
    float arg = (float)pos * invf;
    g_sin[i] = (float)sin((double)arg);
    g_cos[i] = (float)cos((double)arg);
}

// ---------------- LayerNorm -> split bf16 ------------------------------------
__global__ __launch_bounds__(256) void ln_kernel(
    const float* __restrict__ x, const float* __restrict__ ln_g,
    const float* __restrict__ ln_b)
{
    int row = blockIdx.x;
    const float4* xr = (const float4*)(x + (size_t)row * H_);
    float4 v = xr[threadIdx.x];
    float s = v.x + v.y + v.z + v.w;
    float sq = v.x * v.x + v.y * v.y + v.z * v.z + v.w * v.w;
    #pragma unroll
    for (int o = 16; o; o >>= 1) {
        s  += __shfl_down_sync(0xffffffffu, s, o);
        sq += __shfl_down_sync(0xffffffffu, sq, o);
    }
    __shared__ float ss[8], ssq[8];
    int wrp = threadIdx.x >> 5, l = threadIdx.x & 31;
    if (l == 0) { ss[wrp] = s; ssq[wrp] = sq; }
    __syncthreads();
    if (wrp == 0) {
        s  = (l < 8) ? ss[l] : 0.f;
        sq = (l < 8) ? ssq[l] : 0.f;
        #pragma unroll
        for (int o = 4; o; o >>= 1) {
            s  += __shfl_down_sync(0xffu, s, o);
            sq += __shfl_down_sync(0xffu, sq, o);
        }
        if (l == 0) { ss[0] = s; ssq[0] = sq; }
    }
    __syncthreads();
    float mu = ss[0] * (1.f / H_);
    float var = ssq[0] * (1.f / H_) - mu * mu;
    float rs = rsqrtf(var + 1e-5f);
    float4 g = ((const float4*)ln_g)[threadIdx.x];
    float4 bb = ((const float4*)ln_b)[threadIdx.x];
    float o0 = (v.x - mu) * rs * g.x + bb.x;
    float o1 = (v.y - mu) * rs * g.y + bb.y;
    float o2 = (v.z - mu) * rs * g.z + bb.z;
    float o3 = (v.w - mu) * rs * g.w + bb.w;
    uint32_t h0, l0, h1, l1;
    split2(o0, o1, h0, l0);
    split2(o2, o3, h1, l1);
    int idx = row * (H_ / 4) + threadIdx.x;        // uint2 = 4 bf16
    ((uint2*)g_xh)[idx] = make_uint2(h0, h1);
    ((uint2*)g_xl)[idx] = make_uint2(l0, l1);
}

// ---------------- RoPE on base -> q, k (split bf16) --------------------------
__global__ __launch_bounds__(128) void rope_kernel(
    const float* __restrict__ gamma, const float* __restrict__ beta)
{
    int row = blockIdx.x;
    int t = threadIdx.x;
    __shared__ float pq[128], pk[128];
    float base = g_base[(size_t)row * S_ + t];
    pq[t] = base * gamma[t]       + beta[t];
    pk[t] = base * gamma[128 + t] + beta[128 + t];
    __syncthreads();
    int pos = row & (N_ - 1);
    float s, c, x1, x2, r1, r2;
    __nv_bfloat16 bh, bl;
    if (t < 64) {
        s = g_sin[pos * 64 + t]; c = g_cos[pos * 64 + t];
        x1 = pq[t]; x2 = pq[t + 64];
        r1 = x1 * c - x2 * s; r2 = x2 * c + x1 * s;
        size_t o = (size_t)row * S_ + t;
        bh = __float2bfloat16(r1); bl = __float2bfloat16(r1 - __bfloat162float(bh));
        g_qh[o] = bh; g_ql[o] = bl;
        bh = __float2bfloat16(r2); bl = __float2bfloat16(r2 - __bfloat162float(bh));
        g_qh[o + 64] = bh; g_ql[o + 64] = bl;
    } else {
        int d = t - 64;
        s = g_sin[pos * 64 + d]; c = g_cos[pos * 64 + d];
        x1 = pk[d]; x2 = pk[d + 64];
        r1 = x1 * c - x2 * s; r2 = x2 * c + x1 * s;
        size_t o = (size_t)row * S_ + d;
        bh = __float2bfloat16(r1); bl = __float2bfloat16(r1 - __bfloat162float(bh));
        g_kh[o] = bh; g_kl[o] = bl;
        bh = __float2bfloat16(r2); bl = __float2bfloat16(r2 - __bfloat162float(bh));
        g_kh[o + 64] = bh; g_kl[o + 64] = bl;
    }
}

// ---------------- launch -----------------------------------------------------
extern "C" void kernel_launch(void* const* d_in, const int* in_sizes, int n_in,
                              void* d_out, int out_size)
{
    const float* x     = (const float*)d_in[0];
    const float* mask  = (const float*)d_in[1];
    const float* gamma = (const float*)d_in[2];
    const float* beta  = (const float*)d_in[3];
    const float* w     = (const float*)d_in[4];
    const float* uv_w  = (const float*)d_in[7];
    const float* uv_b  = (const float*)d_in[8];
    const float* o_w   = (const float*)d_in[9];
    const float* o_b   = (const float*)d_in[10];
    const float* ln_g  = (const float*)d_in[11];
    const float* ln_b  = (const float*)d_in[12];
    float* out = (float*)d_out;

    cudaFuncSetAttribute(gau_gemm<1, 0>, cudaFuncAttributeMaxDynamicSharedMemorySize, SMEMB);
    cudaFuncSetAttribute(gau_gemm<0, 1>, cudaFuncAttributeMaxDynamicSharedMemorySize, SMEMB);
    cudaFuncSetAttribute(gau_gemm<1, 2>, cudaFuncAttributeMaxDynamicSharedMemorySize, SMEMB);
    cudaFuncSetAttribute(gau_gemm<1, 3>, cudaFuncAttributeMaxDynamicSharedMemorySize, SMEMB);

    __nv_bfloat16 *p_xh, *p_xl, *p_wuh, *p_wul, *p_woh, *p_wol;
    __nv_bfloat16 *p_vh, *p_vl, *p_qh, *p_ql, *p_kh, *p_kl;
    __nv_bfloat16 *p_kerh, *p_kerl, *p_ahh, *p_all;
    cudaGetSymbolAddress((void**)&p_xh,  g_xh);  cudaGetSymbolAddress((void**)&p_xl,  g_xl);
    cudaGetSymbolAddress((void**)&p_wuh, g_wuh); cudaGetSymbolAddress((void**)&p_wul, g_wul);
    cudaGetSymbolAddress((void**)&p_woh, g_woh); cudaGetSymbolAddress((void**)&p_wol, g_wol);
    cudaGetSymbolAddress((void**)&p_vh,  g_vh);  cudaGetSymbolAddress((void**)&p_vl,  g_vl);
    cudaGetSymbolAddress((void**)&p_qh,  g_qh);  cudaGetSymbolAddress((void**)&p_ql,  g_ql);
    cudaGetSymbolAddress((void**)&p_kh,  g_kh);  cudaGetSymbolAddress((void**)&p_kl,  g_kl);
    cudaGetSymbolAddress((void**)&p_kerh,g_kerh);cudaGetSymbolAddress((void**)&p_kerl,g_kerl);
    cudaGetSymbolAddress((void**)&p_ahh, g_ah);  cudaGetSymbolAddress((void**)&p_all, g_al);

    sincos_kernel<<<128, 256>>>();
    split_kernel<<<(H_ * UVW / 2 + 255) / 256, 256>>>(uv_w, p_wuh, p_wul, H_ * UVW / 2);
    split_kernel<<<(E_ * H_ / 2 + 255) / 256, 256>>>(o_w, p_woh, p_wol, E_ * H_ / 2);
    ln_kernel<<<R_, 256>>>(x, ln_g, ln_b);

    // uv = silu(xn @ uv_w + uv_b)        [16384 x 4224 x 1024], B n-contig
    gau_gemm<1, 0><<<dim3(UVW / 128, R_ / 128, 1), 512, SMEMB>>>(
        p_xh, p_xl, H_, 0LL, p_wuh, p_wul, UVW, 0LL, H_, uv_b, nullptr, nullptr);

    rope_kernel<<<R_, 128>>>(gamma, beta);

    // kernel = relu(q@k^T/512 + bias + mask)^2   [512 x 512 x 128] x32, B k-contig
    gau_gemm<0, 1><<<dim3(N_ / 128, N_ / 128, B_), 512, SMEMB>>>(
        p_qh, p_ql, S_, (long long)N_ * S_, p_kh, p_kl, S_, (long long)N_ * S_,
        S_, w, mask, nullptr);

    // attn = u * (kernel @ v)            [512 x 2048 x 512] x32, B n-contig
    gau_gemm<1, 2><<<dim3(E_ / 128, N_ / 128, B_), 512, SMEMB>>>(
        p_kerh, p_kerl, N_, (long long)N_ * N_, p_vh, p_vl, E_, (long long)N_ * E_,
        N_, nullptr, nullptr, nullptr);

    // out = attn @ o_w + o_b + x         [16384 x 1024 x 2048], B n-contig
    gau_gemm<1, 3><<<dim3(H_ / 128, R_ / 128, 1), 512, SMEMB>>>(
        p_ahh, p_all, E_, 0LL, p_woh, p_wol, H_, 0LL, E_, o_b, x, out);
}